// round 1
// baseline (speedup 1.0000x reference)
#include <cuda_runtime.h>
#include <math.h>

// Problem constants
#define BB 2
#define TT 2048
#define CC 1024
#define HH 16
#define DD 64
#define NT (BB*TT)          // 4096 tokens
#define HD (HH*DD)          // 1024

// Scratch: q,k,v,y each [NT, H*D] fp32 (16 MB each)
__device__ float g_q[NT*HD];
__device__ float g_k[NT*HD];
__device__ float g_v[NT*HD];
__device__ float g_y[NT*HD];

// ---------------------------------------------------------------------------
// Tiled SGEMM, 64x64 tile, K-step 16, 256 threads, 4x4 per-thread microtile.
// NT variant: C[m,n] = sum_k A[m*K+k] * B[n*K+k]   (B row-major [N,K])
// NN variant: C[m,n] = sum_k A[m*K+k] * B[k*N+n]   (B row-major [K,N])
// M,N,K assumed multiples of 64/16 (true here: 4096/1024/1024).
// ---------------------------------------------------------------------------
#define TS 64
#define KS 16

__global__ __launch_bounds__(256) void sgemm_nt(
    const float* __restrict__ A, const float* __restrict__ B,
    float* __restrict__ C, int M, int N, int K)
{
    __shared__ float As[KS][TS + 1];
    __shared__ float Bs[KS][TS + 1];

    const int tid = threadIdx.x;
    const int tx = tid & 15;
    const int ty = tid >> 4;
    const int bm = blockIdx.y * TS;
    const int bn = blockIdx.x * TS;

    const int lk = tid & (KS - 1);   // 0..15
    const int lm = tid >> 4;         // 0..15

    float acc[4][4];
#pragma unroll
    for (int i = 0; i < 4; i++)
#pragma unroll
        for (int j = 0; j < 4; j++) acc[i][j] = 0.f;

    for (int k0 = 0; k0 < K; k0 += KS) {
#pragma unroll
        for (int i = 0; i < 4; i++)
            As[lk][lm + i*16] = A[(size_t)(bm + lm + i*16)*K + k0 + lk];
#pragma unroll
        for (int i = 0; i < 4; i++)
            Bs[lk][lm + i*16] = B[(size_t)(bn + lm + i*16)*K + k0 + lk];
        __syncthreads();

#pragma unroll
        for (int k = 0; k < KS; k++) {
            float a[4], b[4];
#pragma unroll
            for (int i = 0; i < 4; i++) a[i] = As[k][ty*4 + i];
#pragma unroll
            for (int j = 0; j < 4; j++) b[j] = Bs[k][tx*4 + j];
#pragma unroll
            for (int i = 0; i < 4; i++)
#pragma unroll
                for (int j = 0; j < 4; j++)
                    acc[i][j] += a[i] * b[j];
        }
        __syncthreads();
    }

#pragma unroll
    for (int i = 0; i < 4; i++)
#pragma unroll
        for (int j = 0; j < 4; j++)
            C[(size_t)(bm + ty*4 + i)*N + bn + tx*4 + j] = acc[i][j];
}

__global__ __launch_bounds__(256) void sgemm_nn(
    const float* __restrict__ A, const float* __restrict__ B,
    float* __restrict__ C, int M, int N, int K)
{
    __shared__ float As[KS][TS + 1];
    __shared__ float Bs[KS][TS + 1];

    const int tid = threadIdx.x;
    const int tx = tid & 15;
    const int ty = tid >> 4;
    const int bm = blockIdx.y * TS;
    const int bn = blockIdx.x * TS;

    const int lk = tid & (KS - 1);
    const int lm = tid >> 4;
    const int lk2 = tid >> 6;        // 0..3
    const int ln  = tid & 63;        // 0..63

    float acc[4][4];
#pragma unroll
    for (int i = 0; i < 4; i++)
#pragma unroll
        for (int j = 0; j < 4; j++) acc[i][j] = 0.f;

    for (int k0 = 0; k0 < K; k0 += KS) {
#pragma unroll
        for (int i = 0; i < 4; i++)
            As[lk][lm + i*16] = A[(size_t)(bm + lm + i*16)*K + k0 + lk];
#pragma unroll
        for (int i = 0; i < 4; i++)
            Bs[lk2 + i*4][ln] = B[(size_t)(k0 + lk2 + i*4)*N + bn + ln];
        __syncthreads();

#pragma unroll
        for (int k = 0; k < KS; k++) {
            float a[4], b[4];
#pragma unroll
            for (int i = 0; i < 4; i++) a[i] = As[k][ty*4 + i];
#pragma unroll
            for (int j = 0; j < 4; j++) b[j] = Bs[k][tx*4 + j];
#pragma unroll
            for (int i = 0; i < 4; i++)
#pragma unroll
                for (int j = 0; j < 4; j++)
                    acc[i][j] += a[i] * b[j];
        }
        __syncthreads();
    }

#pragma unroll
    for (int i = 0; i < 4; i++)
#pragma unroll
        for (int j = 0; j < 4; j++)
            C[(size_t)(bm + ty*4 + i)*N + bn + tx*4 + j] = acc[i][j];
}

// ---------------------------------------------------------------------------
// Causal attention, flash-style online softmax.
// Grid: (T/64, H, B). Block: 64 threads, one thread per query row.
// q,k,v layout: [b*T + t][h*64 + d]  (stride HD=1024 per token)
// y written same layout.
// Dynamic shared: qs[64][65] + ks[64][64] + vs[64][64]  = 49408 bytes
// ---------------------------------------------------------------------------
#define ATTN_SMEM ((64*65 + 64*64 + 64*64) * (int)sizeof(float))

__global__ __launch_bounds__(64) void attn_kernel(
    const float* __restrict__ q, const float* __restrict__ k,
    const float* __restrict__ v, float* __restrict__ y)
{
    extern __shared__ float smem[];
    float* qs = smem;               // [64][65]
    float* ks = smem + 64*65;       // [64][64]
    float* vs = ks + 64*64;         // [64][64]

    const int tid = threadIdx.x;    // 0..63, one query row
    const int rt  = blockIdx.x;     // row tile
    const int h   = blockIdx.y;
    const int b   = blockIdx.z;
    const int row = rt * 64 + tid;
    const float scale = 0.125f;     // 1/sqrt(64)

    // Stage Q tile: qs[r][d], padded pitch 65
    {
        const size_t base = ((size_t)(b*TT + rt*64)) * HD + h*DD;
        for (int idx = tid; idx < 64*64; idx += 64) {
            int r = idx >> 6, d = idx & 63;
            qs[r*65 + d] = q[base + (size_t)r*HD + d];
        }
    }

    float acc[DD];
#pragma unroll
    for (int d = 0; d < DD; d++) acc[d] = 0.f;
    float m = -INFINITY;
    float l = 0.f;

    for (int kt = 0; kt <= rt; kt++) {
        __syncthreads();
        // Stage K/V tiles (coalesced: consecutive threads -> consecutive d)
        const size_t kbase = ((size_t)(b*TT + kt*64)) * HD + h*DD;
        for (int idx = tid; idx < 64*64; idx += 64) {
            int s = idx >> 6, d = idx & 63;
            ks[s*64 + d] = k[kbase + (size_t)s*HD + d];
            vs[s*64 + d] = v[kbase + (size_t)s*HD + d];
        }
        __syncthreads();

        const int jlim = (kt == rt) ? (row - kt*64 + 1) : 64;
        for (int j = 0; j < jlim; j++) {
            float s = 0.f;
            const float* qrow = qs + tid*65;
            const float* krow = ks + j*64;
#pragma unroll
            for (int d = 0; d < DD; d++) s += qrow[d] * krow[d];
            s *= scale;

            if (s > m) {
                float corr = __expf(m - s);   // 0 when m == -inf
                l *= corr;
#pragma unroll
                for (int d = 0; d < DD; d++) acc[d] *= corr;
                m = s;
            }
            float p = __expf(s - m);
            l += p;
            const float* vrow = vs + j*64;
#pragma unroll
            for (int d = 0; d < DD; d++) acc[d] += p * vrow[d];
        }
    }

    // Normalize, stage through shared for coalesced store
    __syncthreads();
    const float inv = 1.0f / l;
#pragma unroll
    for (int d = 0; d < DD; d++) qs[tid*65 + d] = acc[d] * inv;
    __syncthreads();
    {
        const size_t base = ((size_t)(b*TT + rt*64)) * HD + h*DD;
        for (int idx = tid; idx < 64*64; idx += 64) {
            int r = idx >> 6, d = idx & 63;
            y[base + (size_t)r*HD + d] = qs[r*65 + d];
        }
    }
}

// ---------------------------------------------------------------------------
// Launch
// ---------------------------------------------------------------------------
extern "C" void kernel_launch(void* const* d_in, const int* in_sizes, int n_in,
                              void* d_out, int out_size)
{
    const float* x  = (const float*)d_in[0];   // [B,T,C]
    const float* wq = (const float*)d_in[1];   // [H,DQK,C] -> flat [1024,1024]
    const float* wk = (const float*)d_in[2];
    const float* wv = (const float*)d_in[3];
    const float* wo = (const float*)d_in[4];   // [1024,1024]
    float* out = (float*)d_out;                // [B,T,C]

    float *q, *k, *v, *y;
    cudaGetSymbolAddress((void**)&q, g_q);
    cudaGetSymbolAddress((void**)&k, g_k);
    cudaGetSymbolAddress((void**)&v, g_v);
    cudaGetSymbolAddress((void**)&y, g_y);

    dim3 gemm_grid(HD / TS, NT / TS);   // (16, 64)

    // QKV projections: q[nt, h*64+d] = sum_c x[nt,c] * w[h*64+d, c]
    sgemm_nt<<<gemm_grid, 256>>>(x, wq, q, NT, HD, CC);
    sgemm_nt<<<gemm_grid, 256>>>(x, wk, k, NT, HD, CC);
    sgemm_nt<<<gemm_grid, 256>>>(x, wv, v, NT, HD, CC);

    // Causal attention
    cudaFuncSetAttribute(attn_kernel,
                         cudaFuncAttributeMaxDynamicSharedMemorySize, ATTN_SMEM);
    attn_kernel<<<dim3(TT/64, HH, BB), 64, ATTN_SMEM>>>(q, k, v, y);

    // Output projection: out[nt,c] = sum_hd y[nt,hd] * wo[hd,c]
    sgemm_nn<<<gemm_grid, 256>>>(y, wo, out, NT, CC, HD);
}